// round 1
// baseline (speedup 1.0000x reference)
#include <cuda_runtime.h>
#include <math.h>
#include <stdint.h>

// Problem constants
#define BB 512
#define NN 64
#define EE 512
#define AA 16
#define ITERS 8
#define TPB 512          // threads per CTA (one CTA per batch)
#define NC 104           // edges whose 16x16 tiles are cached in SMEM
#define TSTRIDE 17       // padded tile row stride (bank-conflict-free)
#define TWORDS (TSTRIDE * AA)  // 272 floats per tile

// Adjacency (CSR, ascending edge order) -- built once per launch on device.
__device__ int g_to_off[NN + 1], g_from_off[NN + 1];
__device__ int g_to_lst[EE], g_from_lst[EE];

__global__ void build_adj_kernel(const int* __restrict__ ef, const int* __restrict__ et) {
    __shared__ int sf[EE], st[EE];
    __shared__ int cto[NN], cfr[NN];
    int t = threadIdx.x;
    for (int e = t; e < EE; e += blockDim.x) { sf[e] = ef[e]; st[e] = et[e]; }
    __syncthreads();
    if (t < NN) {
        int ct = 0, cf = 0;
        for (int e = 0; e < EE; e++) { ct += (st[e] == t); cf += (sf[e] == t); }
        cto[t] = ct; cfr[t] = cf;
    }
    __syncthreads();
    if (t == 0) {
        int a = 0, b = 0;
        for (int n = 0; n < NN; n++) {
            g_to_off[n] = a; a += cto[n];
            g_from_off[n] = b; b += cfr[n];
        }
        g_to_off[NN] = a; g_from_off[NN] = b;
    }
    __syncthreads();
    if (t < NN) {
        int ot = g_to_off[t], of = g_from_off[t];
        for (int e = 0; e < EE; e++) {
            if (st[e] == t) g_to_lst[ot++] = e;
            if (sf[e] == t) g_from_lst[of++] = e;
        }
    }
}

// SMEM budget (floats):
//  q0:1024  q:1024  mf:8192  mb:8192  cache:NC*272  scratch:32*272
//  red:16  red_node:2  qmax:1   ints: a_cur:64 a_best:64 flag:1 ef:512 et:512
#define SMEM_WORDS (1024 + 1024 + 8192 + 8192 + NC * TWORDS + 32 * TWORDS + 16 + 2 + 1 + 64 + 64 + 1 + 512 + 512)
#define SMEM_BYTES (SMEM_WORDS * 4)

__global__ __launch_bounds__(TPB, 1)
void dcg_kernel(const float* __restrict__ nodev, const float* __restrict__ edgev,
                const int* __restrict__ ef, const int* __restrict__ et,
                float* __restrict__ out)
{
    extern __shared__ float smem[];
    float* q0      = smem;                       // 1024
    float* q       = q0 + 1024;                  // 1024
    float* mf      = q + 1024;                   // 8192
    float* mb      = mf + 8192;                  // 8192
    float* cache   = mb + 8192;                  // NC*272
    float* scratch = cache + NC * TWORDS;        // 32*272
    float* red     = scratch + 32 * TWORDS;      // 16
    float* red_node = red + 16;                  // 2
    float* qmax_s  = red_node + 2;               // 1
    int* a_cur  = (int*)(qmax_s + 1);            // 64
    int* a_best = a_cur + 64;                    // 64
    int* flag   = a_best + 64;                   // 1
    int* ef_s   = flag + 1;                      // 512
    int* et_s   = ef_s + EE;                     // 512

    const int tid    = threadIdx.x;
    const int b      = blockIdx.x;
    const int halfid = tid >> 4;        // 0..31 half-warp id
    const int hl     = tid & 15;        // lane within half-warp
    const unsigned hmask = 0xFFFFu << ((halfid & 1) * 16);
    const int warp = tid >> 5;
    const int lane = tid & 31;

    const float* nb    = nodev + (size_t)b * NN * AA;
    const float* ebase = edgev + (size_t)b * EE * AA * AA;

    // ---- init: q0 = node_vals/64 (exact), q = q0, messages = 0, edge meta, tile cache
    for (int i = tid; i < NN * AA; i += TPB) {
        float v = nb[i] * 0.015625f;   // /64 exact
        q0[i] = v; q[i] = v;
    }
    for (int i = tid; i < EE * AA; i += TPB) { mf[i] = 0.f; mb[i] = 0.f; }
    for (int i = tid; i < EE; i += TPB) { ef_s[i] = ef[i]; et_s[i] = et[i]; }
    for (int i = tid; i < NC * AA * AA; i += TPB) {
        int e = i >> 8, r = (i >> 4) & 15, c = i & 15;
        cache[e * TWORDS + r * TSTRIDE + c] = ebase[i] * (1.0f / 512.0f);  // /E exact
    }
    __syncthreads();

    // ---- argmax of q-array per node (lowest index wins ties, like jnp.argmax)
    auto do_argmax = [&](const float* qa) {
        for (int n = halfid; n < NN; n += 32) {
            float bv = qa[n * AA + hl]; int bi = hl;
            #pragma unroll
            for (int o = 8; o; o >>= 1) {
                float ov = __shfl_xor_sync(hmask, bv, o, 16);
                int   oi = __shfl_xor_sync(hmask, bi, o, 16);
                if (ov > bv || (ov == bv && oi < bi)) { bv = ov; bi = oi; }
            }
            if (hl == 0) a_cur[n] = bi;
        }
    };

    // ---- evaluate action a_cur, update (q_max, a_best). Caller syncs before.
    auto do_eval = [&](bool first) {
        // edge term: thread e gathers edge_vals[b,e,a_f,a_t] (raw = cache*512, exact)
        float ev;
        {
            int e  = tid;
            int af = a_cur[ef_s[e]];
            int at = a_cur[et_s[e]];
            if (e < NC) ev = cache[e * TWORDS + af * TSTRIDE + at] * 512.0f;
            else        ev = ebase[(size_t)e * 256 + af * 16 + at];
        }
        #pragma unroll
        for (int o = 16; o; o >>= 1) ev += __shfl_xor_sync(0xffffffffu, ev, o, 32);
        if (lane == 0) red[warp] = ev;
        // node term: thread n gathers node_vals[b,n,a[n]] = q0*64 (exact)
        if (tid < NN) {
            float nv = q0[tid * AA + a_cur[tid]] * 64.0f;
            #pragma unroll
            for (int o = 16; o; o >>= 1) nv += __shfl_xor_sync(0xffffffffu, nv, o, 32);
            if (lane == 0) red_node[warp] = nv;
        }
        __syncthreads();
        if (tid == 0) {
            float es = 0.f;
            #pragma unroll
            for (int w = 0; w < 16; w++) es += red[w];
            float ns = red_node[0] + red_node[1];
            float qv = ns * (1.0f / 64.0f) + es * (1.0f / 512.0f);
            if (first || qv > *qmax_s) { *qmax_s = qv; *flag = 1; }
            else *flag = 0;
        }
        __syncthreads();
        if (*flag && tid < NN) a_best[tid] = a_cur[tid];
        __syncthreads();
    };

    // ---- initial: a_max = argmax(node_vals) (== argmax q0, exact scale), q_max = eval
    do_argmax(q0);
    __syncthreads();
    do_eval(true);

    // ---- message-passing iterations
    for (int it = 0; it < ITERS; it++) {
        // Phase 1: per-edge messages. Half-warp owns an edge; lane hl is both
        // column at=hl (for mf) and row af=hl (for mb). Tile read once.
        for (int e = halfid; e < EE; e += 32) {
            int nf = ef_s[e], nt = et_s[e];
            float uf = q[nf * AA + hl] - mb[e * AA + hl];   // old mb (same edge)
            float ub = q[nt * AA + hl] - mf[e * AA + hl];   // old mf (same edge)
            const float* tile;
            if (e < NC) tile = cache + e * TWORDS;
            else {
                float* tw = scratch + halfid * TWORDS;
                const float* g = ebase + (size_t)e * 256;
                #pragma unroll
                for (int r = 0; r < 16; r++)
                    tw[r * TSTRIDE + hl] = g[r * 16 + hl] * (1.0f / 512.0f);
                tile = tw;
            }
            __syncwarp(hmask);
            float mfa = -INFINITY, mba = -INFINITY;
            #pragma unroll
            for (int k = 0; k < 16; k++) {
                float ufk = __shfl_sync(hmask, uf, k, 16);
                float ubk = __shfl_sync(hmask, ub, k, 16);
                mfa = fmaxf(mfa, ufk + tile[k * TSTRIDE + hl]);  // column hl
                mba = fmaxf(mba, ubk + tile[hl * TSTRIDE + k]);  // row hl
            }
            // mean-center (tree-sum order deviations are uniform -> argmax-safe)
            float s1 = mfa, s2 = mba;
            #pragma unroll
            for (int o = 8; o; o >>= 1) {
                s1 += __shfl_xor_sync(hmask, s1, o, 16);
                s2 += __shfl_xor_sync(hmask, s2, o, 16);
            }
            mf[e * AA + hl] = mfa - s1 * 0.0625f;
            mb[e * AA + hl] = mba - s2 * 0.0625f;
        }
        __syncthreads();

        // Phase 2: q = q0 + scatter(mf over edges_to) + scatter(mb over edges_from),
        // per node in ascending-edge order (matches XLA scatter application order),
        // then per-node argmax.
        for (int n = halfid; n < NN; n += 32) {
            float acc = q0[n * AA + hl];
            int o0 = g_to_off[n], o1 = g_to_off[n + 1];
            for (int i = o0; i < o1; i++) acc += mf[g_to_lst[i] * AA + hl];
            o0 = g_from_off[n]; o1 = g_from_off[n + 1];
            for (int i = o0; i < o1; i++) acc += mb[g_from_lst[i] * AA + hl];
            q[n * AA + hl] = acc;
            float bv = acc; int bi = hl;
            #pragma unroll
            for (int o = 8; o; o >>= 1) {
                float ov = __shfl_xor_sync(hmask, bv, o, 16);
                int   oi = __shfl_xor_sync(hmask, bi, o, 16);
                if (ov > bv || (ov == bv && oi < bi)) { bv = ov; bi = oi; }
            }
            if (hl == 0) a_cur[n] = bi;
        }
        __syncthreads();

        // Phase 3: evaluate greedy action, keep best
        do_eval(false);
    }

    // ---- output: concat(q_max[B], float(a_max[B,N]))
    if (tid == 0) out[b] = *qmax_s;
    if (tid < NN) out[BB + (size_t)b * NN + tid] = (float)a_best[tid];
}

extern "C" void kernel_launch(void* const* d_in, const int* in_sizes, int n_in,
                              void* d_out, int out_size)
{
    const float* nodev = (const float*)d_in[0];   // (B,N,A) f32
    const float* edgev = (const float*)d_in[1];   // (B,E,A,A) f32
    const int*   ef    = (const int*)d_in[2];     // (E,) i32
    const int*   et    = (const int*)d_in[3];     // (E,) i32
    float* out = (float*)d_out;

    static bool attr_set = false;
    if (!attr_set) {
        cudaFuncSetAttribute(dcg_kernel, cudaFuncAttributeMaxDynamicSharedMemorySize, SMEM_BYTES);
        attr_set = true;
    }

    build_adj_kernel<<<1, 64>>>(ef, et);
    dcg_kernel<<<BB, TPB, SMEM_BYTES>>>(nodev, edgev, ef, et, out);
}

// round 2
// speedup vs baseline: 1.0078x; 1.0078x over previous
#include <cuda_runtime.h>
#include <math.h>
#include <stdint.h>

// Problem constants
#define BB 512
#define NN 64
#define EE 512
#define AA 16
#define ITERS 8
#define TPB 512          // threads per CTA (one CTA per batch)
#define NC 72            // edges whose 16x16 tiles are cached in SMEM
#define TSTRIDE 17       // padded tile row stride (bank-conflict-free)
#define TWORDS (TSTRIDE * AA)  // 272 floats per tile
#define NSCRATCH 64      // 2 staging buffers per half-warp

// Adjacency (CSR, ascending edge order) -- built once per launch on device.
__device__ int g_to_off[NN + 1], g_from_off[NN + 1];
__device__ int g_to_lst[EE], g_from_lst[EE];

__global__ void build_adj_kernel(const int* __restrict__ ef, const int* __restrict__ et) {
    __shared__ int sf[EE], st[EE];
    __shared__ int cto[NN], cfr[NN];
    int t = threadIdx.x;
    for (int e = t; e < EE; e += blockDim.x) { sf[e] = ef[e]; st[e] = et[e]; }
    __syncthreads();
    if (t < NN) {
        int ct = 0, cf = 0;
        for (int e = 0; e < EE; e++) { ct += (st[e] == t); cf += (sf[e] == t); }
        cto[t] = ct; cfr[t] = cf;
    }
    __syncthreads();
    if (t == 0) {
        int a = 0, b = 0;
        for (int n = 0; n < NN; n++) {
            g_to_off[n] = a; a += cto[n];
            g_from_off[n] = b; b += cfr[n];
        }
        g_to_off[NN] = a; g_from_off[NN] = b;
    }
    __syncthreads();
    if (t < NN) {
        int ot = g_to_off[t], of = g_from_off[t];
        for (int e = 0; e < EE; e++) {
            if (st[e] == t) g_to_lst[ot++] = e;
            if (sf[e] == t) g_from_lst[of++] = e;
        }
    }
}

// SMEM budget (floats):
//  q0:1024 q:1024 mf:8192 mb:8192 cache:NC*272 scratch:64*272
//  red:16 red_node:2 qmax:1  ints: a_cur:64 a_best:64 flag:1 ef:512 et:512
#define SMEM_WORDS (1024 + 1024 + 8192 + 8192 + NC * TWORDS + NSCRATCH * TWORDS + 16 + 2 + 1 + 64 + 64 + 1 + 512 + 512)
#define SMEM_BYTES (SMEM_WORDS * 4)

__global__ __launch_bounds__(TPB, 1)
void dcg_kernel(const float* __restrict__ nodev, const float* __restrict__ edgev,
                const int* __restrict__ ef, const int* __restrict__ et,
                float* __restrict__ out)
{
    extern __shared__ float smem[];
    float* q0      = smem;                       // 1024
    float* q       = q0 + 1024;                  // 1024
    float* mf      = q + 1024;                   // 8192
    float* mb      = mf + 8192;                  // 8192
    float* cache   = mb + 8192;                  // NC*272
    float* scratch = cache + NC * TWORDS;        // 64*272
    float* red     = scratch + NSCRATCH * TWORDS; // 16
    float* red_node = red + 16;                  // 2
    float* qmax_s  = red_node + 2;               // 1
    int* a_cur  = (int*)(qmax_s + 1);            // 64
    int* a_best = a_cur + 64;                    // 64
    int* flag   = a_best + 64;                   // 1
    int* ef_s   = flag + 1;                      // 512
    int* et_s   = ef_s + EE;                     // 512

    const int tid    = threadIdx.x;
    const int b      = blockIdx.x;
    const int halfid = tid >> 4;        // 0..31 half-warp id
    const int hl     = tid & 15;        // lane within half-warp
    const unsigned hmask = 0xFFFFu << ((halfid & 1) * 16);
    const int warp = tid >> 5;
    const int lane = tid & 31;

    const float* nb    = nodev + (size_t)b * NN * AA;
    const float* ebase = edgev + (size_t)b * EE * AA * AA;

    // ---- init: q0 = node_vals/64 (exact), q = q0, messages = 0, edge meta, tile cache
    for (int i = tid; i < NN * AA; i += TPB) {
        float v = nb[i] * 0.015625f;   // /64 exact
        q0[i] = v; q[i] = v;
    }
    for (int i = tid; i < EE * AA; i += TPB) { mf[i] = 0.f; mb[i] = 0.f; }
    for (int i = tid; i < EE; i += TPB) { ef_s[i] = ef[i]; et_s[i] = et[i]; }
    for (int i = tid; i < NC * AA * AA; i += TPB) {
        int e = i >> 8, r = (i >> 4) & 15, c = i & 15;
        cache[e * TWORDS + r * TSTRIDE + c] = ebase[i] * (1.0f / 512.0f);  // /E exact
    }
    __syncthreads();

    // ---- argmax of q-array per node (lowest index wins ties, like jnp.argmax)
    auto do_argmax = [&](const float* qa) {
        for (int n = halfid; n < NN; n += 32) {
            float bv = qa[n * AA + hl]; int bi = hl;
            #pragma unroll
            for (int o = 8; o; o >>= 1) {
                float ov = __shfl_xor_sync(hmask, bv, o, 16);
                int   oi = __shfl_xor_sync(hmask, bi, o, 16);
                if (ov > bv || (ov == bv && oi < bi)) { bv = ov; bi = oi; }
            }
            if (hl == 0) a_cur[n] = bi;
        }
    };

    // ---- evaluate action a_cur, update (q_max, a_best). Caller syncs before.
    auto do_eval = [&](bool first) {
        // edge term: thread e gathers edge_vals[b,e,a_f,a_t] (raw = cache*512, exact)
        float ev;
        {
            int e  = tid;
            int af = a_cur[ef_s[e]];
            int at = a_cur[et_s[e]];
            if (e < NC) ev = cache[e * TWORDS + af * TSTRIDE + at] * 512.0f;
            else        ev = ebase[(size_t)e * 256 + af * 16 + at];
        }
        #pragma unroll
        for (int o = 16; o; o >>= 1) ev += __shfl_xor_sync(0xffffffffu, ev, o, 32);
        if (lane == 0) red[warp] = ev;
        // node term: thread n gathers node_vals[b,n,a[n]] = q0*64 (exact)
        if (tid < NN) {
            float nv = q0[tid * AA + a_cur[tid]] * 64.0f;
            #pragma unroll
            for (int o = 16; o; o >>= 1) nv += __shfl_xor_sync(0xffffffffu, nv, o, 32);
            if (lane == 0) red_node[warp] = nv;
        }
        __syncthreads();
        if (tid == 0) {
            float es = 0.f;
            #pragma unroll
            for (int w = 0; w < 16; w++) es += red[w];
            float ns = red_node[0] + red_node[1];
            float qv = ns * (1.0f / 64.0f) + es * (1.0f / 512.0f);
            if (first || qv > *qmax_s) { *qmax_s = qv; *flag = 1; }
            else *flag = 0;
        }
        __syncthreads();
        if (*flag && tid < NN) a_best[tid] = a_cur[tid];
        __syncthreads();
    };

    // ---- initial: a_max = argmax(node_vals) (== argmax q0, exact scale), q_max = eval
    do_argmax(q0);
    __syncthreads();
    do_eval(true);

    // ---- message-passing iterations
    for (int it = 0; it < ITERS; it++) {
        // Phase 1: per-edge messages. Half-warp owns TWO edges (e0, e0+256)
        // concurrently for latency hiding. Lane hl is both column at=hl (mf)
        // and row af=hl (mb).
        for (int i = 0; i < 8; i++) {
            const int e0 = halfid + 32 * i;
            const int e1 = e0 + 256;
            const int nf0 = ef_s[e0], nt0 = et_s[e0];
            const int nf1 = ef_s[e1], nt1 = et_s[e1];
            float uf0 = q[nf0 * AA + hl] - mb[e0 * AA + hl];
            float ub0 = q[nt0 * AA + hl] - mf[e0 * AA + hl];
            float uf1 = q[nf1 * AA + hl] - mb[e1 * AA + hl];
            float ub1 = q[nt1 * AA + hl] - mf[e1 * AA + hl];

            // tile pointers (stage uncached tiles from L2 into scratch)
            const float* t0;
            float* tw1 = scratch + (halfid + 32) * TWORDS;  // slot j=1
            const float* g1 = ebase + (size_t)e1 * 256;
            if (e0 < NC) {
                t0 = cache + e0 * TWORDS;
                #pragma unroll
                for (int r = 0; r < 16; r++)
                    tw1[r * TSTRIDE + hl] = g1[r * 16 + hl] * (1.0f / 512.0f);
            } else {
                float* tw0 = scratch + halfid * TWORDS;     // slot j=0
                const float* g0 = ebase + (size_t)e0 * 256;
                #pragma unroll
                for (int r = 0; r < 16; r++) {
                    tw0[r * TSTRIDE + hl] = g0[r * 16 + hl] * (1.0f / 512.0f);
                    tw1[r * TSTRIDE + hl] = g1[r * 16 + hl] * (1.0f / 512.0f);
                }
                t0 = tw0;
            }
            const float* t1 = tw1;
            __syncwarp(hmask);

            // max-plus, 8 independent accumulator chains (exact reassociation of fmax)
            float f0a = -INFINITY, f0b = -INFINITY, b0a = -INFINITY, b0b = -INFINITY;
            float f1a = -INFINITY, f1b = -INFINITY, b1a = -INFINITY, b1b = -INFINITY;
            #pragma unroll
            for (int k = 0; k < 8; k++) {
                const int k2 = k + 8;
                float uf0k  = __shfl_sync(hmask, uf0, k,  16);
                float uf0k2 = __shfl_sync(hmask, uf0, k2, 16);
                float ub0k  = __shfl_sync(hmask, ub0, k,  16);
                float ub0k2 = __shfl_sync(hmask, ub0, k2, 16);
                float uf1k  = __shfl_sync(hmask, uf1, k,  16);
                float uf1k2 = __shfl_sync(hmask, uf1, k2, 16);
                float ub1k  = __shfl_sync(hmask, ub1, k,  16);
                float ub1k2 = __shfl_sync(hmask, ub1, k2, 16);
                f0a = fmaxf(f0a, uf0k  + t0[k  * TSTRIDE + hl]);
                f0b = fmaxf(f0b, uf0k2 + t0[k2 * TSTRIDE + hl]);
                b0a = fmaxf(b0a, ub0k  + t0[hl * TSTRIDE + k ]);
                b0b = fmaxf(b0b, ub0k2 + t0[hl * TSTRIDE + k2]);
                f1a = fmaxf(f1a, uf1k  + t1[k  * TSTRIDE + hl]);
                f1b = fmaxf(f1b, uf1k2 + t1[k2 * TSTRIDE + hl]);
                b1a = fmaxf(b1a, ub1k  + t1[hl * TSTRIDE + k ]);
                b1b = fmaxf(b1b, ub1k2 + t1[hl * TSTRIDE + k2]);
            }
            float mfa0 = fmaxf(f0a, f0b), mba0 = fmaxf(b0a, b0b);
            float mfa1 = fmaxf(f1a, f1b), mba1 = fmaxf(b1a, b1b);

            // mean-center: 4 interleaved butterflies (order-uniform -> argmax-safe)
            float s0f = mfa0, s0b = mba0, s1f = mfa1, s1b = mba1;
            #pragma unroll
            for (int o = 8; o; o >>= 1) {
                s0f += __shfl_xor_sync(hmask, s0f, o, 16);
                s0b += __shfl_xor_sync(hmask, s0b, o, 16);
                s1f += __shfl_xor_sync(hmask, s1f, o, 16);
                s1b += __shfl_xor_sync(hmask, s1b, o, 16);
            }
            mf[e0 * AA + hl] = mfa0 - s0f * 0.0625f;
            mb[e0 * AA + hl] = mba0 - s0b * 0.0625f;
            mf[e1 * AA + hl] = mfa1 - s1f * 0.0625f;
            mb[e1 * AA + hl] = mba1 - s1b * 0.0625f;
        }
        __syncthreads();

        // Phase 2: q = q0 + scatter(mf over edges_to) + scatter(mb over edges_from),
        // per node in ascending-edge order, then per-node argmax.
        for (int n = halfid; n < NN; n += 32) {
            float acc = q0[n * AA + hl];
            int o0 = g_to_off[n], o1 = g_to_off[n + 1];
            for (int i = o0; i < o1; i++) acc += mf[g_to_lst[i] * AA + hl];
            o0 = g_from_off[n]; o1 = g_from_off[n + 1];
            for (int i = o0; i < o1; i++) acc += mb[g_from_lst[i] * AA + hl];
            q[n * AA + hl] = acc;
            float bv = acc; int bi = hl;
            #pragma unroll
            for (int o = 8; o; o >>= 1) {
                float ov = __shfl_xor_sync(hmask, bv, o, 16);
                int   oi = __shfl_xor_sync(hmask, bi, o, 16);
                if (ov > bv || (ov == bv && oi < bi)) { bv = ov; bi = oi; }
            }
            if (hl == 0) a_cur[n] = bi;
        }
        __syncthreads();

        // Phase 3: evaluate greedy action, keep best
        do_eval(false);
    }

    // ---- output: concat(q_max[B], float(a_max[B,N]))
    if (tid == 0) out[b] = *qmax_s;
    if (tid < NN) out[BB + (size_t)b * NN + tid] = (float)a_best[tid];
}

extern "C" void kernel_launch(void* const* d_in, const int* in_sizes, int n_in,
                              void* d_out, int out_size)
{
    const float* nodev = (const float*)d_in[0];   // (B,N,A) f32
    const float* edgev = (const float*)d_in[1];   // (B,E,A,A) f32
    const int*   ef    = (const int*)d_in[2];     // (E,) i32
    const int*   et    = (const int*)d_in[3];     // (E,) i32
    float* out = (float*)d_out;

    static bool attr_set = false;
    if (!attr_set) {
        cudaFuncSetAttribute(dcg_kernel, cudaFuncAttributeMaxDynamicSharedMemorySize, SMEM_BYTES);
        attr_set = true;
    }

    build_adj_kernel<<<1, 64>>>(ef, et);
    dcg_kernel<<<BB, TPB, SMEM_BYTES>>>(nodev, edgev, ef, et, out);
}

// round 5
// speedup vs baseline: 1.0550x; 1.0468x over previous
#include <cuda_runtime.h>
#include <math.h>
#include <stdint.h>

// Problem constants
#define BB 512
#define NN 64
#define EE 512
#define AA 16
#define ITERS 8
#define TPB 512          // threads per CTA (one CTA per batch)
#define SLOTW 36         // floats per half-warp u-slot (144B: bank-offsets the two halves)
#define EINV (1.0f / 512.0f)

// Adjacency (CSR, ascending edge order) -- built once per launch on device.
__device__ int g_to_off[NN + 1], g_from_off[NN + 1];
__device__ int g_to_lst[EE], g_from_lst[EE];

__global__ void build_adj_kernel(const int* __restrict__ ef, const int* __restrict__ et) {
    __shared__ int sf[EE], st[EE];
    __shared__ int cto[NN], cfr[NN];
    int t = threadIdx.x;
    for (int e = t; e < EE; e += blockDim.x) { sf[e] = ef[e]; st[e] = et[e]; }
    __syncthreads();
    if (t < NN) {
        int ct = 0, cf = 0;
        for (int e = 0; e < EE; e++) { ct += (st[e] == t); cf += (sf[e] == t); }
        cto[t] = ct; cfr[t] = cf;
    }
    __syncthreads();
    if (t == 0) {
        int a = 0, b = 0;
        for (int n = 0; n < NN; n++) {
            g_to_off[n] = a; a += cto[n];
            g_from_off[n] = b; b += cfr[n];
        }
        g_to_off[NN] = a; g_from_off[NN] = b;
    }
    __syncthreads();
    if (t < NN) {
        int ot = g_to_off[t], of = g_from_off[t];
        for (int e = 0; e < EE; e++) {
            if (st[e] == t) g_to_lst[ot++] = e;
            if (sf[e] == t) g_from_lst[of++] = e;
        }
    }
}

// SMEM layout (floats):
//  ubuf: 32*SLOTW = 1152   (16B-aligned base; uf at +0, ub at +16 per slot)
//  q0:1024  q:1024  mf:8192  mb:8192
//  red:16  red_node:2  qmax:1  ints: a_cur:64 a_best:64 flag:1 ef:512 et:512
#define SMEM_WORDS (32 * SLOTW + 1024 + 1024 + 8192 + 8192 + 16 + 2 + 1 + 64 + 64 + 1 + 512 + 512)
// pad to 120KB to pin occupancy at 1 CTA/SM (keeps concurrent edge tiles inside L2)
#define SMEM_BYTES (120 * 1024)

__global__ __launch_bounds__(TPB, 1)
void dcg_kernel(const float* __restrict__ nodev, const float* __restrict__ edgev,
                const int* __restrict__ ef, const int* __restrict__ et,
                float* __restrict__ out)
{
    extern __shared__ float smem[];
    float* ubuf    = smem;                        // 1152 (16B aligned)
    float* q0      = ubuf + 32 * SLOTW;           // 1024
    float* q       = q0 + 1024;                   // 1024
    float* mf      = q + 1024;                    // 8192
    float* mb      = mf + 8192;                   // 8192
    float* red     = mb + 8192;                   // 16
    float* red_node = red + 16;                   // 2
    float* qmax_s  = red_node + 2;                // 1
    int* a_cur  = (int*)(qmax_s + 1);             // 64
    int* a_best = a_cur + 64;                     // 64
    int* flag   = a_best + 64;                    // 1
    int* ef_s   = flag + 1;                       // 512
    int* et_s   = ef_s + EE;                      // 512

    const int tid    = threadIdx.x;
    const int b      = blockIdx.x;
    const int halfid = tid >> 4;        // 0..31 half-warp id
    const int hl     = tid & 15;        // lane within half-warp
    const unsigned hmask = 0xFFFFu << ((halfid & 1) * 16);
    const int warp = tid >> 5;
    const int lane = tid & 31;
    const int slot = halfid * SLOTW;

    const float* nb    = nodev + (size_t)b * NN * AA;
    const float* ebase = edgev + (size_t)b * EE * AA * AA;

    // ---- init
    for (int i = tid; i < NN * AA; i += TPB) {
        float v = nb[i] * 0.015625f;   // /64 exact
        q0[i] = v; q[i] = v;
    }
    for (int i = tid; i < EE * AA; i += TPB) { mf[i] = 0.f; mb[i] = 0.f; }
    for (int i = tid; i < EE; i += TPB) { ef_s[i] = ef[i]; et_s[i] = et[i]; }
    __syncthreads();

    // ---- argmax of q-array per node (lowest index wins ties, like jnp.argmax)
    auto do_argmax = [&](const float* qa) {
        for (int n = halfid; n < NN; n += 32) {
            float bv = qa[n * AA + hl]; int bi = hl;
            #pragma unroll
            for (int o = 8; o; o >>= 1) {
                float ov = __shfl_xor_sync(hmask, bv, o, 16);
                int   oi = __shfl_xor_sync(hmask, bi, o, 16);
                if (ov > bv || (ov == bv && oi < bi)) { bv = ov; bi = oi; }
            }
            if (hl == 0) a_cur[n] = bi;
        }
    };

    // ---- evaluate action a_cur, update (q_max, a_best). Caller syncs before.
    auto do_eval = [&](bool first) {
        float ev;
        {
            int e  = tid;
            int af = a_cur[ef_s[e]];
            int at = a_cur[et_s[e]];
            ev = ebase[(size_t)e * 256 + af * 16 + at];
        }
        #pragma unroll
        for (int o = 16; o; o >>= 1) ev += __shfl_xor_sync(0xffffffffu, ev, o, 32);
        if (lane == 0) red[warp] = ev;
        if (tid < NN) {
            float nv = q0[tid * AA + a_cur[tid]] * 64.0f;   // node_vals exact
            #pragma unroll
            for (int o = 16; o; o >>= 1) nv += __shfl_xor_sync(0xffffffffu, nv, o, 32);
            if (lane == 0) red_node[warp] = nv;
        }
        __syncthreads();
        if (tid == 0) {
            float es = 0.f;
            #pragma unroll
            for (int w = 0; w < 16; w++) es += red[w];
            float ns = red_node[0] + red_node[1];
            float qv = ns * (1.0f / 64.0f) + es * (1.0f / 512.0f);
            if (first || qv > *qmax_s) { *qmax_s = qv; *flag = 1; }
            else *flag = 0;
        }
        __syncthreads();
        if (*flag && tid < NN) a_best[tid] = a_cur[tid];
        __syncthreads();
    };

    // ---- initial: a_max = argmax(node_vals), q_max = eval
    do_argmax(q0);
    __syncthreads();
    do_eval(true);

    // ---- message-passing iterations
    for (int it = 0; it < ITERS; it++) {
        // Phase 1: one edge per half-warp per pass.
        // Lane hl is output index for both mf (at=hl) and mb (af=hl).
        for (int pass = 0; pass < 16; ++pass) {
            const int e = halfid + 32 * pass;
            const int nf = ef_s[e], nt = et_s[e];
            const float mbe = mb[e * AA + hl];
            const float mfe = mf[e * AA + hl];
            const float ufv = q[nf * AA + hl] - mbe;
            const float ubv = q[nt * AA + hl] - mfe;
            ubuf[slot + hl]      = ufv;
            ubuf[slot + 16 + hl] = ubv;

            const float* g  = ebase + (size_t)e * 256;
            const float4* g4 = (const float4*)g;
            // row hl of T (for mb): 4x LDG.128
            float4 r0 = g4[hl * 4 + 0];
            float4 r1 = g4[hl * 4 + 1];
            float4 r2 = g4[hl * 4 + 2];
            float4 r3 = g4[hl * 4 + 3];
            // column hl of T (for mf): 16 coalesced LDG.32
            float c0 = g[ 0*16+hl], c1 = g[ 1*16+hl], c2 = g[ 2*16+hl], c3 = g[ 3*16+hl];
            float c4 = g[ 4*16+hl], c5 = g[ 5*16+hl], c6 = g[ 6*16+hl], c7 = g[ 7*16+hl];
            float c8 = g[ 8*16+hl], c9 = g[ 9*16+hl], cA = g[10*16+hl], cB = g[11*16+hl];
            float cC = g[12*16+hl], cD = g[13*16+hl], cE = g[14*16+hl], cF = g[15*16+hl];

            __syncwarp();
            const float4* uv4 = (const float4*)(ubuf + slot);
            float4 uf0 = uv4[0], uf1 = uv4[1], uf2 = uv4[2], uf3 = uv4[3];
            float4 ub0 = uv4[4], ub1 = uv4[5], ub2 = uv4[6], ub3 = uv4[7];

            // max-plus: two split accumulators per direction (exact fmax reassoc);
            // u + T*(1/512) via FMA == reference's u + (T/512): product is exact.
            float fa, fb, ba, bb;
            fa = fmaf(c0, EINV, uf0.x);
            fa = fmaxf(fa, fmaf(c1, EINV, uf0.y));
            fa = fmaxf(fa, fmaf(c2, EINV, uf0.z));
            fa = fmaxf(fa, fmaf(c3, EINV, uf0.w));
            fa = fmaxf(fa, fmaf(c4, EINV, uf1.x));
            fa = fmaxf(fa, fmaf(c5, EINV, uf1.y));
            fa = fmaxf(fa, fmaf(c6, EINV, uf1.z));
            fa = fmaxf(fa, fmaf(c7, EINV, uf1.w));
            fb = fmaf(c8, EINV, uf2.x);
            fb = fmaxf(fb, fmaf(c9, EINV, uf2.y));
            fb = fmaxf(fb, fmaf(cA, EINV, uf2.z));
            fb = fmaxf(fb, fmaf(cB, EINV, uf2.w));
            fb = fmaxf(fb, fmaf(cC, EINV, uf3.x));
            fb = fmaxf(fb, fmaf(cD, EINV, uf3.y));
            fb = fmaxf(fb, fmaf(cE, EINV, uf3.z));
            fb = fmaxf(fb, fmaf(cF, EINV, uf3.w));
            ba = fmaf(r0.x, EINV, ub0.x);
            ba = fmaxf(ba, fmaf(r0.y, EINV, ub0.y));
            ba = fmaxf(ba, fmaf(r0.z, EINV, ub0.z));
            ba = fmaxf(ba, fmaf(r0.w, EINV, ub0.w));
            ba = fmaxf(ba, fmaf(r1.x, EINV, ub1.x));
            ba = fmaxf(ba, fmaf(r1.y, EINV, ub1.y));
            ba = fmaxf(ba, fmaf(r1.z, EINV, ub1.z));
            ba = fmaxf(ba, fmaf(r1.w, EINV, ub1.w));
            bb = fmaf(r2.x, EINV, ub2.x);
            bb = fmaxf(bb, fmaf(r2.y, EINV, ub2.y));
            bb = fmaxf(bb, fmaf(r2.z, EINV, ub2.z));
            bb = fmaxf(bb, fmaf(r2.w, EINV, ub2.w));
            bb = fmaxf(bb, fmaf(r3.x, EINV, ub3.x));
            bb = fmaxf(bb, fmaf(r3.y, EINV, ub3.y));
            bb = fmaxf(bb, fmaf(r3.z, EINV, ub3.z));
            bb = fmaxf(bb, fmaf(r3.w, EINV, ub3.w));
            float mfa = fmaxf(fa, fb);
            float mba = fmaxf(ba, bb);

            // mean-center (order-uniform per edge -> argmax-safe)
            float sf = mfa, sb = mba;
            #pragma unroll
            for (int o = 8; o; o >>= 1) {
                sf += __shfl_xor_sync(hmask, sf, o, 16);
                sb += __shfl_xor_sync(hmask, sb, o, 16);
            }
            mf[e * AA + hl] = mfa - sf * 0.0625f;
            mb[e * AA + hl] = mba - sb * 0.0625f;
            // butterflies sync'd the half-warp: safe to overwrite ubuf next pass
        }
        __syncthreads();

        // Phase 2: q = q0 + scatter(mf over edges_to) + scatter(mb over edges_from)
        // per node in ascending-edge order, then per-node argmax.
        for (int n = halfid; n < NN; n += 32) {
            float acc = q0[n * AA + hl];
            int o0 = g_to_off[n], o1 = g_to_off[n + 1];
            for (int i = o0; i < o1; i++) acc += mf[g_to_lst[i] * AA + hl];
            o0 = g_from_off[n]; o1 = g_from_off[n + 1];
            for (int i = o0; i < o1; i++) acc += mb[g_from_lst[i] * AA + hl];
            q[n * AA + hl] = acc;
            float bv = acc; int bi = hl;
            #pragma unroll
            for (int o = 8; o; o >>= 1) {
                float ov = __shfl_xor_sync(hmask, bv, o, 16);
                int   oi = __shfl_xor_sync(hmask, bi, o, 16);
                if (ov > bv || (ov == bv && oi < bi)) { bv = ov; bi = oi; }
            }
            if (hl == 0) a_cur[n] = bi;
        }
        __syncthreads();

        // Phase 3: evaluate greedy action, keep best
        do_eval(false);
    }

    // ---- output: concat(q_max[B], float(a_max[B,N]))
    if (tid == 0) out[b] = *qmax_s;
    if (tid < NN) out[BB + (size_t)b * NN + tid] = (float)a_best[tid];
}

extern "C" void kernel_launch(void* const* d_in, const int* in_sizes, int n_in,
                              void* d_out, int out_size)
{
    const float* nodev = (const float*)d_in[0];   // (B,N,A) f32
    const float* edgev = (const float*)d_in[1];   // (B,E,A,A) f32
    const int*   ef    = (const int*)d_in[2];     // (E,) i32
    const int*   et    = (const int*)d_in[3];     // (E,) i32
    float* out = (float*)d_out;

    static bool attr_set = false;
    if (!attr_set) {
        cudaFuncSetAttribute(dcg_kernel, cudaFuncAttributeMaxDynamicSharedMemorySize, SMEM_BYTES);
        attr_set = true;
    }

    build_adj_kernel<<<1, 64>>>(ef, et);
    dcg_kernel<<<BB, TPB, SMEM_BYTES>>>(nodev, edgev, ef, et, out);
}

// round 7
// speedup vs baseline: 1.1364x; 1.0772x over previous
#include <cuda_runtime.h>
#include <math.h>
#include <stdint.h>

// Problem constants
#define BB 512
#define NN 64
#define EE 512
#define AA 16
#define ITERS 8
#define TPB 512          // threads per CTA (one CTA per batch)
#define SLOTW 36         // floats per half-warp u-slot (144B: bank-offsets the two halves)
#define EINV (1.0f / 512.0f)

// Adjacency (CSR, ascending edge order) -- built once per launch on device.
__device__ int g_to_off[NN + 1], g_from_off[NN + 1];
__device__ int g_to_lst[EE], g_from_lst[EE];

__global__ void build_adj_kernel(const int* __restrict__ ef, const int* __restrict__ et) {
    __shared__ int sf[EE], st[EE];
    __shared__ int cto[NN], cfr[NN];
    int t = threadIdx.x;
    for (int e = t; e < EE; e += blockDim.x) { sf[e] = ef[e]; st[e] = et[e]; }
    __syncthreads();
    if (t < NN) {
        int ct = 0, cf = 0;
        for (int e = 0; e < EE; e++) { ct += (st[e] == t); cf += (sf[e] == t); }
        cto[t] = ct; cfr[t] = cf;
    }
    __syncthreads();
    if (t == 0) {
        int a = 0, b = 0;
        for (int n = 0; n < NN; n++) {
            g_to_off[n] = a; a += cto[n];
            g_from_off[n] = b; b += cfr[n];
        }
        g_to_off[NN] = a; g_from_off[NN] = b;
    }
    __syncthreads();
    if (t < NN) {
        int ot = g_to_off[t], of = g_from_off[t];
        for (int e = 0; e < EE; e++) {
            if (st[e] == t) g_to_lst[ot++] = e;
            if (sf[e] == t) g_from_lst[of++] = e;
        }
    }
}

// SMEM layout (floats):
//  ubuf: 32*SLOTW = 1152   (16B-aligned base; uf at +0, ub at +16 per slot)
//  q0:1024  q:1024  mf:8192  mb:8192
//  red:16  red_node:2  qmax:1  ints: a_cur:64 a_best:64 flag:1 ef:512 et:512
#define SMEM_WORDS (32 * SLOTW + 1024 + 1024 + 8192 + 8192 + 16 + 2 + 1 + 64 + 64 + 1 + 512 + 512)
// exact size (~83KB) -> 2 CTAs per SM
#define SMEM_BYTES (SMEM_WORDS * 4)

__global__ __launch_bounds__(TPB, 2)
void dcg_kernel(const float* __restrict__ nodev, const float* __restrict__ edgev,
                const int* __restrict__ ef, const int* __restrict__ et,
                float* __restrict__ out)
{
    extern __shared__ float smem[];
    float* ubuf    = smem;                        // 1152 (16B aligned)
    float* q0      = ubuf + 32 * SLOTW;           // 1024
    float* q       = q0 + 1024;                   // 1024
    float* mf      = q + 1024;                    // 8192
    float* mb      = mf + 8192;                   // 8192
    float* red     = mb + 8192;                   // 16
    float* red_node = red + 16;                   // 2
    float* qmax_s  = red_node + 2;                // 1
    int* a_cur  = (int*)(qmax_s + 1);             // 64
    int* a_best = a_cur + 64;                     // 64
    int* flag   = a_best + 64;                    // 1
    int* ef_s   = flag + 1;                       // 512
    int* et_s   = ef_s + EE;                      // 512

    const int tid    = threadIdx.x;
    const int b      = blockIdx.x;
    const int halfid = tid >> 4;        // 0..31 half-warp id
    const int hl     = tid & 15;        // lane within half-warp
    const unsigned hmask = 0xFFFFu << ((halfid & 1) * 16);
    const int warp = tid >> 5;
    const int lane = tid & 31;
    const int slot = halfid * SLOTW;

    const float* nb    = nodev + (size_t)b * NN * AA;
    const float* ebase = edgev + (size_t)b * EE * AA * AA;

    // ---- init
    for (int i = tid; i < NN * AA; i += TPB) {
        float v = nb[i] * 0.015625f;   // /64 exact
        q0[i] = v; q[i] = v;
    }
    for (int i = tid; i < EE * AA; i += TPB) { mf[i] = 0.f; mb[i] = 0.f; }
    for (int i = tid; i < EE; i += TPB) { ef_s[i] = ef[i]; et_s[i] = et[i]; }
    __syncthreads();

    // ---- argmax of q-array per node (lowest index wins ties, like jnp.argmax)
    auto do_argmax = [&](const float* qa) {
        for (int n = halfid; n < NN; n += 32) {
            float bv = qa[n * AA + hl]; int bi = hl;
            #pragma unroll
            for (int o = 8; o; o >>= 1) {
                float ov = __shfl_xor_sync(hmask, bv, o, 16);
                int   oi = __shfl_xor_sync(hmask, bi, o, 16);
                if (ov > bv || (ov == bv && oi < bi)) { bv = ov; bi = oi; }
            }
            if (hl == 0) a_cur[n] = bi;
        }
    };

    // ---- evaluate action a_cur, update (q_max, a_best). Caller syncs before.
    auto do_eval = [&](bool first) {
        float ev;
        {
            int e  = tid;
            int af = a_cur[ef_s[e]];
            int at = a_cur[et_s[e]];
            ev = ebase[(size_t)e * 256 + af * 16 + at];
        }
        #pragma unroll
        for (int o = 16; o; o >>= 1) ev += __shfl_xor_sync(0xffffffffu, ev, o, 32);
        if (lane == 0) red[warp] = ev;
        if (tid < NN) {
            float nv = q0[tid * AA + a_cur[tid]] * 64.0f;   // node_vals exact
            #pragma unroll
            for (int o = 16; o; o >>= 1) nv += __shfl_xor_sync(0xffffffffu, nv, o, 32);
            if (lane == 0) red_node[warp] = nv;
        }
        __syncthreads();
        if (tid == 0) {
            float es = 0.f;
            #pragma unroll
            for (int w = 0; w < 16; w++) es += red[w];
            float ns = red_node[0] + red_node[1];
            float qv = ns * (1.0f / 64.0f) + es * (1.0f / 512.0f);
            if (first || qv > *qmax_s) { *qmax_s = qv; *flag = 1; }
            else *flag = 0;
        }
        __syncthreads();
        if (*flag && tid < NN) a_best[tid] = a_cur[tid];
        __syncthreads();
    };

    // ---- initial: a_max = argmax(node_vals), q_max = eval
    do_argmax(q0);
    __syncthreads();
    do_eval(true);

    // ---- message-passing iterations
    for (int it = 0; it < ITERS; it++) {
        // Phase 1: one edge per half-warp per pass. Split into a row half
        // (compute mb) then a column half (compute mf) to cap live registers
        // at <=64 so 2 CTAs/SM fit without spills. Math identical to before.
        for (int pass = 0; pass < 16; ++pass) {
            const int e = halfid + 32 * pass;
            const int nf = ef_s[e], nt = et_s[e];
            const float mbe = mb[e * AA + hl];   // old mb
            const float mfe = mf[e * AA + hl];   // old mf
            const float ufv = q[nf * AA + hl] - mbe;
            const float ubv = q[nt * AA + hl] - mfe;
            ubuf[slot + hl]      = ufv;
            ubuf[slot + 16 + hl] = ubv;

            const float* g  = ebase + (size_t)e * 256;
            const float4* g4 = (const float4*)g;
            const float4* uv4 = (const float4*)(ubuf + slot);
            __syncwarp();

            // ---- row half: mb[hl] = max_k(ub[k] + T[hl][k]/E)
            {
                float4 r0 = g4[hl * 4 + 0];
                float4 r1 = g4[hl * 4 + 1];
                float4 r2 = g4[hl * 4 + 2];
                float4 r3 = g4[hl * 4 + 3];
                float4 ub0 = uv4[4], ub1 = uv4[5], ub2 = uv4[6], ub3 = uv4[7];
                float ba, bb;
                ba = fmaf(r0.x, EINV, ub0.x);
                ba = fmaxf(ba, fmaf(r0.y, EINV, ub0.y));
                ba = fmaxf(ba, fmaf(r0.z, EINV, ub0.z));
                ba = fmaxf(ba, fmaf(r0.w, EINV, ub0.w));
                ba = fmaxf(ba, fmaf(r1.x, EINV, ub1.x));
                ba = fmaxf(ba, fmaf(r1.y, EINV, ub1.y));
                ba = fmaxf(ba, fmaf(r1.z, EINV, ub1.z));
                ba = fmaxf(ba, fmaf(r1.w, EINV, ub1.w));
                bb = fmaf(r2.x, EINV, ub2.x);
                bb = fmaxf(bb, fmaf(r2.y, EINV, ub2.y));
                bb = fmaxf(bb, fmaf(r2.z, EINV, ub2.z));
                bb = fmaxf(bb, fmaf(r2.w, EINV, ub2.w));
                bb = fmaxf(bb, fmaf(r3.x, EINV, ub3.x));
                bb = fmaxf(bb, fmaf(r3.y, EINV, ub3.y));
                bb = fmaxf(bb, fmaf(r3.z, EINV, ub3.z));
                bb = fmaxf(bb, fmaf(r3.w, EINV, ub3.w));
                float mba = fmaxf(ba, bb);
                float sb = mba;
                #pragma unroll
                for (int o = 8; o; o >>= 1)
                    sb += __shfl_xor_sync(hmask, sb, o, 16);
                mb[e * AA + hl] = mba - sb * 0.0625f;
            }

            // ---- column half: mf[hl] = max_k(uf[k] + T[k][hl]/E)
            {
                float c0 = g[ 0*16+hl], c1 = g[ 1*16+hl], c2 = g[ 2*16+hl], c3 = g[ 3*16+hl];
                float c4 = g[ 4*16+hl], c5 = g[ 5*16+hl], c6 = g[ 6*16+hl], c7 = g[ 7*16+hl];
                float c8 = g[ 8*16+hl], c9 = g[ 9*16+hl], cA = g[10*16+hl], cB = g[11*16+hl];
                float cC = g[12*16+hl], cD = g[13*16+hl], cE = g[14*16+hl], cF = g[15*16+hl];
                float4 uf0 = uv4[0], uf1 = uv4[1], uf2 = uv4[2], uf3 = uv4[3];
                float fa, fb;
                fa = fmaf(c0, EINV, uf0.x);
                fa = fmaxf(fa, fmaf(c1, EINV, uf0.y));
                fa = fmaxf(fa, fmaf(c2, EINV, uf0.z));
                fa = fmaxf(fa, fmaf(c3, EINV, uf0.w));
                fa = fmaxf(fa, fmaf(c4, EINV, uf1.x));
                fa = fmaxf(fa, fmaf(c5, EINV, uf1.y));
                fa = fmaxf(fa, fmaf(c6, EINV, uf1.z));
                fa = fmaxf(fa, fmaf(c7, EINV, uf1.w));
                fb = fmaf(c8, EINV, uf2.x);
                fb = fmaxf(fb, fmaf(c9, EINV, uf2.y));
                fb = fmaxf(fb, fmaf(cA, EINV, uf2.z));
                fb = fmaxf(fb, fmaf(cB, EINV, uf2.w));
                fb = fmaxf(fb, fmaf(cC, EINV, uf3.x));
                fb = fmaxf(fb, fmaf(cD, EINV, uf3.y));
                fb = fmaxf(fb, fmaf(cE, EINV, uf3.z));
                fb = fmaxf(fb, fmaf(cF, EINV, uf3.w));
                float mfa = fmaxf(fa, fb);
                float sf = mfa;
                #pragma unroll
                for (int o = 8; o; o >>= 1)
                    sf += __shfl_xor_sync(hmask, sf, o, 16);
                mf[e * AA + hl] = mfa - sf * 0.0625f;
            }
            // butterflies sync'd the half-warp: safe to overwrite ubuf next pass
        }
        __syncthreads();

        // Phase 2: q = q0 + scatter(mf over edges_to) + scatter(mb over edges_from)
        // per node in ascending-edge order, then per-node argmax.
        for (int n = halfid; n < NN; n += 32) {
            float acc = q0[n * AA + hl];
            int o0 = g_to_off[n], o1 = g_to_off[n + 1];
            for (int i = o0; i < o1; i++) acc += mf[g_to_lst[i] * AA + hl];
            o0 = g_from_off[n]; o1 = g_from_off[n + 1];
            for (int i = o0; i < o1; i++) acc += mb[g_from_lst[i] * AA + hl];
            q[n * AA + hl] = acc;
            float bv = acc; int bi = hl;
            #pragma unroll
            for (int o = 8; o; o >>= 1) {
                float ov = __shfl_xor_sync(hmask, bv, o, 16);
                int   oi = __shfl_xor_sync(hmask, bi, o, 16);
                if (ov > bv || (ov == bv && oi < bi)) { bv = ov; bi = oi; }
            }
            if (hl == 0) a_cur[n] = bi;
        }
        __syncthreads();

        // Phase 3: evaluate greedy action, keep best
        do_eval(false);
    }

    // ---- output: concat(q_max[B], float(a_max[B,N]))
    if (tid == 0) out[b] = *qmax_s;
    if (tid < NN) out[BB + (size_t)b * NN + tid] = (float)a_best[tid];
}

extern "C" void kernel_launch(void* const* d_in, const int* in_sizes, int n_in,
                              void* d_out, int out_size)
{
    const float* nodev = (const float*)d_in[0];   // (B,N,A) f32
    const float* edgev = (const float*)d_in[1];   // (B,E,A,A) f32
    const int*   ef    = (const int*)d_in[2];     // (E,) i32
    const int*   et    = (const int*)d_in[3];     // (E,) i32
    float* out = (float*)d_out;

    static bool attr_set = false;
    if (!attr_set) {
        cudaFuncSetAttribute(dcg_kernel, cudaFuncAttributeMaxDynamicSharedMemorySize, SMEM_BYTES);
        attr_set = true;
    }

    build_adj_kernel<<<1, 64>>>(ef, et);
    dcg_kernel<<<BB, TPB, SMEM_BYTES>>>(nodev, edgev, ef, et, out);
}

// round 8
// speedup vs baseline: 1.3349x; 1.1746x over previous
#include <cuda_runtime.h>
#include <math.h>
#include <stdint.h>

// Problem constants
#define BB 512
#define NN 64
#define EE 512
#define AA 16
#define ITERS 8
#define TPB 512          // threads per CTA (one CTA per batch)
#define EINV (1.0f / 512.0f)

// Adjacency (CSR, ascending edge order) -- built once per launch on device.
__device__ int g_to_off[NN + 1], g_from_off[NN + 1];
__device__ int g_to_lst[EE], g_from_lst[EE];

__global__ void build_adj_kernel(const int* __restrict__ ef, const int* __restrict__ et) {
    __shared__ int sf[EE], st[EE];
    __shared__ int cto[NN], cfr[NN];
    int t = threadIdx.x;
    for (int e = t; e < EE; e += blockDim.x) { sf[e] = ef[e]; st[e] = et[e]; }
    __syncthreads();
    if (t < NN) {
        int ct = 0, cf = 0;
        for (int e = 0; e < EE; e++) { ct += (st[e] == t); cf += (sf[e] == t); }
        cto[t] = ct; cfr[t] = cf;
    }
    __syncthreads();
    if (t == 0) {
        int a = 0, b = 0;
        for (int n = 0; n < NN; n++) {
            g_to_off[n] = a; a += cto[n];
            g_from_off[n] = b; b += cfr[n];
        }
        g_to_off[NN] = a; g_from_off[NN] = b;
    }
    __syncthreads();
    if (t < NN) {
        int ot = g_to_off[t], of = g_from_off[t];
        for (int e = 0; e < EE; e++) {
            if (st[e] == t) g_to_lst[ot++] = e;
            if (sf[e] == t) g_from_lst[of++] = e;
        }
    }
}

// SMEM layout (floats):
//  q0:1024  q:1024  mf:8192  mb:8192
//  red:16 red_node:2 qmax:1  ints: a_cur:64 a_best:64 flag:1 ef:512 et:512
#define SMEM_WORDS (1024 + 1024 + 8192 + 8192 + 16 + 2 + 1 + 64 + 64 + 1 + 512 + 512)
#define SMEM_BYTES (SMEM_WORDS * 4)    // ~76.6KB -> 2 CTAs per SM

__device__ __forceinline__ float4 f4_fmaf(float4 a, float4 c) {
    // a*EINV + c  (single rounding per element, == reference's add of exact T/E)
    float4 r;
    r.x = fmaf(a.x, EINV, c.x); r.y = fmaf(a.y, EINV, c.y);
    r.z = fmaf(a.z, EINV, c.z); r.w = fmaf(a.w, EINV, c.w);
    return r;
}
__device__ __forceinline__ float4 f4_fmafs(float4 a, float c) {
    float4 r;
    r.x = fmaf(a.x, EINV, c); r.y = fmaf(a.y, EINV, c);
    r.z = fmaf(a.z, EINV, c); r.w = fmaf(a.w, EINV, c);
    return r;
}
__device__ __forceinline__ float4 f4_max(float4 a, float4 b) {
    float4 r;
    r.x = fmaxf(a.x, b.x); r.y = fmaxf(a.y, b.y);
    r.z = fmaxf(a.z, b.z); r.w = fmaxf(a.w, b.w);
    return r;
}
__device__ __forceinline__ float4 f4_sub(float4 a, float4 b) {
    float4 r;
    r.x = a.x - b.x; r.y = a.y - b.y; r.z = a.z - b.z; r.w = a.w - b.w;
    return r;
}

__global__ __launch_bounds__(TPB, 2)
void dcg_kernel(const float* __restrict__ nodev, const float* __restrict__ edgev,
                const int* __restrict__ ef, const int* __restrict__ et,
                float* __restrict__ out)
{
    extern __shared__ float smem[];
    float* q0      = smem;                        // 1024
    float* q       = q0 + 1024;                   // 1024
    float* mf      = q + 1024;                    // 8192
    float* mb      = mf + 8192;                   // 8192
    float* red     = mb + 8192;                   // 16
    float* red_node = red + 16;                   // 2
    float* qmax_s  = red_node + 2;                // 1
    int* a_cur  = (int*)(qmax_s + 1);             // 64
    int* a_best = a_cur + 64;                     // 64
    int* flag   = a_best + 64;                    // 1
    int* ef_s   = flag + 1;                       // 512
    int* et_s   = ef_s + EE;                      // 512

    const int tid    = threadIdx.x;
    const int b      = blockIdx.x;
    const int halfid = tid >> 4;        // 0..31 half-warp id
    const int hl     = tid & 15;        // lane within half-warp
    const unsigned hmask = 0xFFFFu << ((halfid & 1) * 16);
    const int warp = tid >> 5;
    const int lane = tid & 31;

    const float* nb    = nodev + (size_t)b * NN * AA;
    const float* ebase = edgev + (size_t)b * EE * AA * AA;

    // ---- init
    for (int i = tid; i < NN * AA; i += TPB) {
        float v = nb[i] * 0.015625f;   // /64 exact
        q0[i] = v; q[i] = v;
    }
    for (int i = tid; i < EE * AA; i += TPB) { mf[i] = 0.f; mb[i] = 0.f; }
    for (int i = tid; i < EE; i += TPB) { ef_s[i] = ef[i]; et_s[i] = et[i]; }
    __syncthreads();

    // ---- argmax of q-array per node (lowest index wins ties, like jnp.argmax)
    auto do_argmax = [&](const float* qa) {
        for (int n = halfid; n < NN; n += 32) {
            float bv = qa[n * AA + hl]; int bi = hl;
            #pragma unroll
            for (int o = 8; o; o >>= 1) {
                float ov = __shfl_xor_sync(hmask, bv, o, 16);
                int   oi = __shfl_xor_sync(hmask, bi, o, 16);
                if (ov > bv || (ov == bv && oi < bi)) { bv = ov; bi = oi; }
            }
            if (hl == 0) a_cur[n] = bi;
        }
    };

    // ---- evaluate action a_cur, update (q_max, a_best). Caller syncs before.
    auto do_eval = [&](bool first) {
        float ev;
        {
            int e  = tid;
            int af = a_cur[ef_s[e]];
            int at = a_cur[et_s[e]];
            ev = ebase[(size_t)e * 256 + af * 16 + at];
        }
        #pragma unroll
        for (int o = 16; o; o >>= 1) ev += __shfl_xor_sync(0xffffffffu, ev, o, 32);
        if (lane == 0) red[warp] = ev;
        if (tid < NN) {
            float nv = q0[tid * AA + a_cur[tid]] * 64.0f;   // node_vals exact
            #pragma unroll
            for (int o = 16; o; o >>= 1) nv += __shfl_xor_sync(0xffffffffu, nv, o, 32);
            if (lane == 0) red_node[warp] = nv;
        }
        __syncthreads();
        if (tid == 0) {
            float es = 0.f;
            #pragma unroll
            for (int w = 0; w < 16; w++) es += red[w];
            float ns = red_node[0] + red_node[1];
            float qv = ns * (1.0f / 64.0f) + es * (1.0f / 512.0f);
            if (first || qv > *qmax_s) { *qmax_s = qv; *flag = 1; }
            else *flag = 0;
        }
        __syncthreads();
        if (*flag && tid < NN) a_best[tid] = a_cur[tid];
        __syncthreads();
    };

    // ---- initial: a_max = argmax(node_vals), q_max = eval
    do_argmax(q0);
    __syncthreads();
    do_eval(true);

    // ---- message-passing iterations
    for (int it = 0; it < ITERS; it++) {
        // Phase 1: one edge per half-warp per pass. Lane hl holds ROW hl of
        // the tile only (4 LDG.128). mb computed in-register with broadcast
        // ub; mf via 15-shuffle max reduce-scatter (fmax is exact-assoc, so
        // any tree is bitwise identical to the reference max).
        for (int pass = 0; pass < 16; ++pass) {
            const int e = halfid + 32 * pass;
            const int nf = ef_s[e], nt = et_s[e];

            // per-lane uf scalar (lane hl is row af=hl)
            const float ufs = q[nf * AA + hl] - mb[e * AA + hl];

            // ub vector: broadcast loads (same address across half-warp)
            const float4* qnt4 = (const float4*)(q  + nt * AA);
            const float4* mfo4 = (const float4*)(mf + e  * AA);
            float4 UB0 = f4_sub(qnt4[0], mfo4[0]);
            float4 UB1 = f4_sub(qnt4[1], mfo4[1]);
            float4 UB2 = f4_sub(qnt4[2], mfo4[2]);
            float4 UB3 = f4_sub(qnt4[3], mfo4[3]);

            // row hl of T: 4x LDG.128
            const float4* g4 = (const float4*)(ebase + (size_t)e * 256) + hl * 4;
            float4 R0 = g4[0], R1 = g4[1], R2 = g4[2], R3 = g4[3];

            // mb[hl] = max_at(ub[at] + T[hl][at]/E)  -- fully in-register
            float4 m4 = f4_fmaf(R0, UB0);
            m4 = f4_max(m4, f4_fmaf(R1, UB1));
            m4 = f4_max(m4, f4_fmaf(R2, UB2));
            m4 = f4_max(m4, f4_fmaf(R3, UB3));
            float mba = fmaxf(fmaxf(m4.x, m4.y), fmaxf(m4.z, m4.w));

            // mf candidates: cand[at] = uf[hl] + T[hl][at]/E
            float4 C0 = f4_fmafs(R0, ufs);
            float4 C1 = f4_fmafs(R1, ufs);
            float4 C2 = f4_fmafs(R2, ufs);
            float4 C3 = f4_fmafs(R3, ufs);

            // max reduce-scatter over the 16 rows; lane hl ends with mf[hl].
            // Round 1 (offset 8): keep the 8 cols matching own bit3.
            const bool b8 = (hl & 8) != 0;
            float4 kA = b8 ? C2 : C0, kB = b8 ? C3 : C1;
            float4 sA = b8 ? C0 : C2, sB = b8 ? C1 : C3;
            sA.x = __shfl_xor_sync(hmask, sA.x, 8, 16);
            sA.y = __shfl_xor_sync(hmask, sA.y, 8, 16);
            sA.z = __shfl_xor_sync(hmask, sA.z, 8, 16);
            sA.w = __shfl_xor_sync(hmask, sA.w, 8, 16);
            sB.x = __shfl_xor_sync(hmask, sB.x, 8, 16);
            sB.y = __shfl_xor_sync(hmask, sB.y, 8, 16);
            sB.z = __shfl_xor_sync(hmask, sB.z, 8, 16);
            sB.w = __shfl_xor_sync(hmask, sB.w, 8, 16);
            float4 w0 = f4_max(kA, sA);
            float4 w1 = f4_max(kB, sB);
            // Round 2 (offset 4)
            const bool b4 = (hl & 4) != 0;
            float4 k4 = b4 ? w1 : w0, s4 = b4 ? w0 : w1;
            s4.x = __shfl_xor_sync(hmask, s4.x, 4, 16);
            s4.y = __shfl_xor_sync(hmask, s4.y, 4, 16);
            s4.z = __shfl_xor_sync(hmask, s4.z, 4, 16);
            s4.w = __shfl_xor_sync(hmask, s4.w, 4, 16);
            float4 x4 = f4_max(k4, s4);
            // Round 3 (offset 2)
            const bool b2 = (hl & 2) != 0;
            float ky0 = b2 ? x4.z : x4.x, ky1 = b2 ? x4.w : x4.y;
            float sy0 = b2 ? x4.x : x4.z, sy1 = b2 ? x4.y : x4.w;
            sy0 = __shfl_xor_sync(hmask, sy0, 2, 16);
            sy1 = __shfl_xor_sync(hmask, sy1, 2, 16);
            float y0 = fmaxf(ky0, sy0), y1 = fmaxf(ky1, sy1);
            // Round 4 (offset 1)
            const bool b1 = (hl & 1) != 0;
            float kz = b1 ? y1 : y0, sz = b1 ? y0 : y1;
            sz = __shfl_xor_sync(hmask, sz, 1, 16);
            float mfa = fmaxf(kz, sz);

            // mean-center (same butterfly tree as prior rounds -> bitwise id)
            float sfv = mfa, sbv = mba;
            #pragma unroll
            for (int o = 8; o; o >>= 1) {
                sfv += __shfl_xor_sync(hmask, sfv, o, 16);
                sbv += __shfl_xor_sync(hmask, sbv, o, 16);
            }
            mf[e * AA + hl] = mfa - sfv * 0.0625f;
            mb[e * AA + hl] = mba - sbv * 0.0625f;
            // anti-dependences (read m_old before write) are enforced by the
            // shfl data-flow: every lane's writes follow shuffles that require
            // every other lane's loads to have completed.
        }
        __syncthreads();

        // Phase 2: q = q0 + scatter(mf over edges_to) + scatter(mb over edges_from)
        // per node in ascending-edge order, then per-node argmax.
        for (int n = halfid; n < NN; n += 32) {
            float acc = q0[n * AA + hl];
            int o0 = g_to_off[n], o1 = g_to_off[n + 1];
            for (int i = o0; i < o1; i++) acc += mf[g_to_lst[i] * AA + hl];
            o0 = g_from_off[n]; o1 = g_from_off[n + 1];
            for (int i = o0; i < o1; i++) acc += mb[g_from_lst[i] * AA + hl];
            q[n * AA + hl] = acc;
            float bv = acc; int bi = hl;
            #pragma unroll
            for (int o = 8; o; o >>= 1) {
                float ov = __shfl_xor_sync(hmask, bv, o, 16);
                int   oi = __shfl_xor_sync(hmask, bi, o, 16);
                if (ov > bv || (ov == bv && oi < bi)) { bv = ov; bi = oi; }
            }
            if (hl == 0) a_cur[n] = bi;
        }
        __syncthreads();

        // Phase 3: evaluate greedy action, keep best
        do_eval(false);
    }

    // ---- output: concat(q_max[B], float(a_max[B,N]))
    if (tid == 0) out[b] = *qmax_s;
    if (tid < NN) out[BB + (size_t)b * NN + tid] = (float)a_best[tid];
}

extern "C" void kernel_launch(void* const* d_in, const int* in_sizes, int n_in,
                              void* d_out, int out_size)
{
    const float* nodev = (const float*)d_in[0];   // (B,N,A) f32
    const float* edgev = (const float*)d_in[1];   // (B,E,A,A) f32
    const int*   ef    = (const int*)d_in[2];     // (E,) i32
    const int*   et    = (const int*)d_in[3];     // (E,) i32
    float* out = (float*)d_out;

    static bool attr_set = false;
    if (!attr_set) {
        cudaFuncSetAttribute(dcg_kernel, cudaFuncAttributeMaxDynamicSharedMemorySize, SMEM_BYTES);
        attr_set = true;
    }

    build_adj_kernel<<<1, 64>>>(ef, et);
    dcg_kernel<<<BB, TPB, SMEM_BYTES>>>(nodev, edgev, ef, et, out);
}